// round 6
// baseline (speedup 1.0000x reference)
#include <cuda_runtime.h>
#include <math.h>

// Problem dims
#define B_   16
#define H_   128
#define W_   64
#define T_   64
#define NLOC (B_ * H_ * W_)

// Scratch
__device__ unsigned long long g_xbits[NLOC];
__device__ unsigned long long g_s1bits[NLOC];
__device__ float              g_psp[T_ * NLOC];   // [t][loc] layout

// ---------------------------------------------------------------------------
// Kernel 0: pack input floats (exactly 0.0 / 1.0) into per-neuron bitmasks.
// ---------------------------------------------------------------------------
__global__ void __launch_bounds__(256) pack_kernel(const float* __restrict__ in) {
    const int lane = threadIdx.x & 31;
    const int w0   = threadIdx.x & 32;
    const int h    = blockIdx.x * 4 + threadIdx.y;
    const int b    = blockIdx.y;
    const int loc0 = (b * H_ + h) * W_ + w0;
    const size_t gbase = (size_t)loc0 * T_;

    unsigned lo = 0u, hi = 0u;
#pragma unroll
    for (int i = 0; i < 64; ++i) {
        float v = in[gbase + i * 32 + lane];
        unsigned bal = __ballot_sync(0xffffffffu, v != 0.0f);
        if (lane == (i >> 1)) {
            if (i & 1) hi = bal; else lo = bal;
        }
    }
    g_xbits[loc0 + lane] = ((unsigned long long)hi << 32) | (unsigned long long)lo;
}

// ---------------------------------------------------------------------------
// PSP kernel: temporal FIR over binary spike bits.
//   psp[t] = sum_j K[j] * bit(t-j)
// Products exact (x in {0,1}); summation ascending contraction index =
// DESCENDING lag j (cuDNN/XLA direct 1xK conv: sequential ascending k).
// ---------------------------------------------------------------------------
template <int LAYER>
__global__ void __launch_bounds__(256) psp_kernel() {
    constexpr int FIRN = (LAYER == 0) ? 8 : 16;
    const double tau   = (LAYER == 0) ? 1.0 : 2.0;

    __shared__ float s_k[FIRN];
    if (threadIdx.x < FIRN) {
        double td = (double)threadIdx.x;
        s_k[threadIdx.x] = (float)(((1.0 * td) / tau) * exp(1.0 - td / tau));
    }
    __syncthreads();

    const int loc = blockIdx.x * 256 + threadIdx.x;
    const unsigned long long m = (LAYER == 0) ? g_xbits[loc] : g_s1bits[loc];

    float kk[FIRN];
#pragma unroll
    for (int k = 0; k < FIRN; ++k) kk[k] = s_k[k];

#pragma unroll
    for (int t = 0; t < T_; ++t) {
        float acc = 0.0f;
#pragma unroll
        for (int k = 0; k < FIRN; ++k) {        // ascending contraction index
            int j = FIRN - 1 - k;               // = descending lag j
            if (j <= t && ((m >> (t - j)) & 1ull)) acc = __fadd_rn(acc, kk[j]);
        }
        g_psp[t * NLOC + loc] = acc;
    }
}

// ---------------------------------------------------------------------------
// Scan kernel: 3x3 conv via Winograd F(2x2,3x3), canonical Lavin order:
//   V = (B^T d) B   (rows-within-column first, then across columns)
//   U = (G g) G^T   with exact-half form 0.5*((g0+g2)+-g1)
//   M = U .* V      (C=K=1: elementwise only, no channel reduction)
//   Y = (A^T M) A   left-associated 3-term sums
// Then exact replication of slayer getSpikes (time-ordered refractory).
// ---------------------------------------------------------------------------
template <int LAYER>
__global__ void __launch_bounds__(256) scan_kernel(const float* __restrict__ wconv,
                                                   float* __restrict__ out) {
    constexpr int   JMAX  = (LAYER == 0) ? 17 : 35;
    constexpr float THETA = (LAYER == 0) ? 30.0f : 50.0f;

    __shared__ float s_rk[JMAX + 1];
    __shared__ float s_w[9];

    const int tid = threadIdx.y * 64 + threadIdx.x;
    {
        const double tau   = (LAYER == 0) ? 1.0 : 2.0;
        const double rmult = (LAYER == 0) ? -60.0 : -100.0;   // -2*theta*scale_ref
        if (tid <= JMAX) {
            double td = (double)tid;
            double v  = ((rmult * td) / tau) * exp(1.0 - td / tau);
            s_rk[tid] = (tid == 0) ? 0.0f : (float)v;
        }
        if (tid < 9) s_w[tid] = wconv[tid];
    }
    __syncthreads();

    const int w = threadIdx.x;
    const int h = blockIdx.x * 4 + threadIdx.y;
    const int b = blockIdx.y;
    const int loc = (b * H_ + h) * W_ + w;
    const int bbase = b * H_ * W_;

    // ---- weight transform U = G g G^T (identical in every thread) ----
    float U[4][4];
    {
        float q[4][3];
#pragma unroll
        for (int j = 0; j < 3; ++j) {
            float g0 = s_w[j], g1 = s_w[3 + j], g2 = s_w[6 + j];
            float s  = __fadd_rn(g0, g2);
            q[0][j] = g0;
            q[1][j] = __fmul_rn(0.5f, __fadd_rn(s, g1));
            q[2][j] = __fmul_rn(0.5f, __fsub_rn(s, g1));
            q[3][j] = g2;
        }
#pragma unroll
        for (int i = 0; i < 4; ++i) {
            float q0 = q[i][0], q1 = q[i][1], q2 = q[i][2];
            float s  = __fadd_rn(q0, q2);
            U[i][0] = q0;
            U[i][1] = __fmul_rn(0.5f, __fadd_rn(s, q1));
            U[i][2] = __fmul_rn(0.5f, __fsub_rn(s, q1));
            U[i][3] = q2;
        }
    }

    // ---- tile geometry: this thread's output lives in tile (h>>1, w>>1) ----
    const int r0 = 2 * (h >> 1) - 1;          // input tile top row
    const int c0 = 2 * (w >> 1) - 1;          // input tile left col
    const int ph = h & 1, pw = w & 1;         // position within 2x2 output tile
    bool rv[4], cv[4];
#pragma unroll
    for (int r = 0; r < 4; ++r) rv[r] = ((unsigned)(r0 + r) < (unsigned)H_);
#pragma unroll
    for (int c = 0; c < 4; ++c) cv[c] = ((unsigned)(c0 + c) < (unsigned)W_);

    float fut[T_];
#pragma unroll
    for (int t = 0; t < T_; ++t) fut[t] = 0.0f;

    unsigned long long sm = 0ull;

#pragma unroll
    for (int t = 0; t < T_; ++t) {
        const float* pt = g_psp + t * NLOC + bbase;

        // load 4x4 tile (zeros at borders) and apply B^T (rows within column)
        float tt[4][4];
#pragma unroll
        for (int c = 0; c < 4; ++c) {
            const int gc = c0 + c;
            float x0 = (rv[0] && cv[c]) ? pt[(r0 + 0) * W_ + gc] : 0.0f;
            float x1 = (rv[1] && cv[c]) ? pt[(r0 + 1) * W_ + gc] : 0.0f;
            float x2 = (rv[2] && cv[c]) ? pt[(r0 + 2) * W_ + gc] : 0.0f;
            float x3 = (rv[3] && cv[c]) ? pt[(r0 + 3) * W_ + gc] : 0.0f;
            tt[0][c] = __fsub_rn(x0, x2);
            tt[1][c] = __fadd_rn(x1, x2);
            tt[2][c] = __fsub_rn(x2, x1);
            tt[3][c] = __fsub_rn(x1, x3);
        }

        // V = tt * B (across columns), M = U.*V, s_j = (A^T M)_ph,j
        float s[4];
#pragma unroll
        for (int j = 0; j < 4; ++j) {
            float M[4];
#pragma unroll
            for (int i = 0; i < 4; ++i) {
                float t0 = tt[i][0], t1 = tt[i][1], t2 = tt[i][2], t3 = tt[i][3];
                float Vij = (j == 0) ? __fsub_rn(t0, t2)
                          : (j == 1) ? __fadd_rn(t1, t2)
                          : (j == 2) ? __fsub_rn(t2, t1)
                                     : __fsub_rn(t1, t3);
                M[i] = __fmul_rn(U[i][j], Vij);
            }
            s[j] = (ph == 0) ? __fadd_rn(__fadd_rn(M[0], M[1]), M[2])
                             : __fsub_rn(__fsub_rn(M[1], M[2]), M[3]);
        }
        float u = (pw == 0) ? __fadd_rn(__fadd_rn(s[0], s[1]), s[2])
                            : __fsub_rn(__fsub_rn(s[1], s[2]), s[3]);

        // membrane + refractory, threshold, future-refractory accumulation
        float m = __fadd_rn(u, fut[t]);
        if (m >= THETA) {
            sm |= (1ull << t);
#pragma unroll
            for (int j = 1; j <= JMAX; ++j)
                if (t + j < T_) fut[t + j] = __fadd_rn(fut[t + j], s_rk[j]);
        }
    }

    if (LAYER == 0) {
        g_s1bits[loc] = sm;
    } else {
        // expand bits -> floats with coalesced stores (warp shuffle transpose)
        const int lane = w & 31;
        const int loc0 = loc - lane;
        const size_t gbase = (size_t)loc0 * T_;
        const unsigned lo32 = (unsigned)sm;
        const unsigned hi32 = (unsigned)(sm >> 32);
#pragma unroll
        for (int i = 0; i < 64; ++i) {
            int j = i >> 1;
            unsigned half = __shfl_sync(0xffffffffu, (i & 1) ? hi32 : lo32, j);
            out[gbase + i * 32 + lane] = ((half >> lane) & 1u) ? 1.0f : 0.0f;
        }
    }
}

// ---------------------------------------------------------------------------
extern "C" void kernel_launch(void* const* d_in, const int* in_sizes, int n_in,
                              void* d_out, int out_size) {
    const float* x  = (const float*)d_in[0];
    const float* w1 = (const float*)d_in[1];
    const float* w2 = (const float*)d_in[2];
    float* out = (float*)d_out;

    dim3 blk(64, 4);
    dim3 grd(H_ / 4, B_);
    dim3 pblk(256);
    dim3 pgrd(NLOC / 256);

    pack_kernel<<<grd, blk>>>(x);
    psp_kernel<0><<<pgrd, pblk>>>();
    scan_kernel<0><<<grd, blk>>>(w1, nullptr);
    psp_kernel<1><<<pgrd, pblk>>>();
    scan_kernel<1><<<grd, blk>>>(w2, out);
}

// round 7
// speedup vs baseline: 2.5381x; 2.5381x over previous
#include <cuda_runtime.h>
#include <math.h>

// Problem dims
#define B_   16
#define H_   128
#define W_   64
#define T_   64
#define NLOC (B_ * H_ * W_)

// Scratch: spike bitmasks (1 bit per timestep)
__device__ unsigned long long g_xbits[NLOC];
__device__ unsigned long long g_s1bits[NLOC];

// ---------------------------------------------------------------------------
// Kernel 0: pack input floats (exactly 0.0 / 1.0) into per-neuron bitmasks.
// ---------------------------------------------------------------------------
__global__ void __launch_bounds__(256) pack_kernel(const float* __restrict__ in) {
    const int lane = threadIdx.x & 31;
    const int w0   = threadIdx.x & 32;
    const int h    = blockIdx.x * 4 + threadIdx.y;
    const int b    = blockIdx.y;
    const int loc0 = (b * H_ + h) * W_ + w0;
    const size_t gbase = (size_t)loc0 * T_;

    unsigned lo = 0u, hi = 0u;
#pragma unroll
    for (int i = 0; i < 64; ++i) {
        float v = in[gbase + i * 32 + lane];
        unsigned bal = __ballot_sync(0xffffffffu, v != 0.0f);
        if (lane == (i >> 1)) {
            if (i & 1) hi = bal; else lo = bal;
        }
    }
    g_xbits[loc0 + lane] = ((unsigned long long)hi << 32) | (unsigned long long)lo;
}

// ---------------------------------------------------------------------------
// Fused layer kernel: psp (temporal FIR over bits, computed per-block into a
// double-buffered smem halo tile, descending-lag order = ascending contraction
// index — bit-identical to the standalone psp kernel) + Winograd F(2x2,3x3)
// conv (exact same op sequence as R6) + spike scan with refractory computed
// as r = sum_{j=JMAX..1} rk[j]*spike(t-j) — sequential adds in spike-time-
// ascending order, bit-identical to the reference buffer scan.
// ---------------------------------------------------------------------------
template <int LAYER>
__global__ void __launch_bounds__(256, 2) fused_kernel(const float* __restrict__ wconv,
                                                       float* __restrict__ out) {
    constexpr int   FIRN  = (LAYER == 0) ? 8 : 16;
    constexpr int   JMAX  = (LAYER == 0) ? 17 : 35;
    constexpr float THETA = (LAYER == 0) ? 30.0f : 50.0f;
    constexpr int   NHALO = 6 * 66;                 // halo rows x cols

    __shared__ float s_kk[FIRN];
    __shared__ float s_rk[JMAX + 1];
    __shared__ float s_w[9];
    __shared__ float s_psp[2][6][72];               // double-buffered psp tile

    const int tx  = threadIdx.x;
    const int ty  = threadIdx.y;
    const int tid = ty * 64 + tx;
    const int h0  = blockIdx.x * 4;
    const int b   = blockIdx.y;

    // --- taps, computed in double to match numpy exactly ---
    {
        const double tau   = (LAYER == 0) ? 1.0 : 2.0;
        const double rmult = (LAYER == 0) ? -60.0 : -100.0;   // -2*theta*scale_ref
        if (tid < FIRN) {
            double td = (double)tid;
            s_kk[tid] = (float)(((1.0 * td) / tau) * exp(1.0 - td / tau));
        }
        if (tid <= JMAX) {
            double td = (double)tid;
            double v  = ((rmult * td) / tau) * exp(1.0 - td / tau);
            s_rk[tid] = (tid == 0) ? 0.0f : (float)v;
        }
        if (tid < 9) s_w[tid] = wconv[tid];
    }
    __syncthreads();

    float kk[FIRN];
#pragma unroll
    for (int k = 0; k < FIRN; ++k) kk[k] = s_kk[k];
    float rk[JMAX + 1];
#pragma unroll
    for (int j = 0; j <= JMAX; ++j) rk[j] = s_rk[j];

    // --- weight transform U = G g G^T, exact-half form (identical to R6) ---
    float U[4][4];
    {
        float q[4][3];
#pragma unroll
        for (int j = 0; j < 3; ++j) {
            float g0 = s_w[j], g1 = s_w[3 + j], g2 = s_w[6 + j];
            float s  = __fadd_rn(g0, g2);
            q[0][j] = g0;
            q[1][j] = __fmul_rn(0.5f, __fadd_rn(s, g1));
            q[2][j] = __fmul_rn(0.5f, __fsub_rn(s, g1));
            q[3][j] = g2;
        }
#pragma unroll
        for (int i = 0; i < 4; ++i) {
            float q0 = q[i][0], q1 = q[i][1], q2 = q[i][2];
            float s  = __fadd_rn(q0, q2);
            U[i][0] = q0;
            U[i][1] = __fmul_rn(0.5f, __fadd_rn(s, q1));
            U[i][2] = __fmul_rn(0.5f, __fsub_rn(s, q1));
            U[i][3] = q2;
        }
    }

    // --- halo bitmask load: rows h0-1..h0+4, cols -1..64, zeros outside ---
    const unsigned long long* bits = (LAYER == 0) ? g_xbits : g_s1bits;
    const int i0 = tid, i1 = tid + 256;
    const int hr0 = i0 / 66, hc0 = i0 % 66;
    const int hr1 = i1 / 66, hc1 = i1 % 66;

    unsigned long long m0 = 0ull, m1 = 0ull;
    {
        int grow = h0 - 1 + hr0, gcol = hc0 - 1;
        if ((unsigned)grow < (unsigned)H_ && (unsigned)gcol < (unsigned)W_)
            m0 = bits[(b * H_ + grow) * W_ + gcol];
        if (i1 < NHALO) {
            grow = h0 - 1 + hr1; gcol = hc1 - 1;
            if ((unsigned)grow < (unsigned)H_ && (unsigned)gcol < (unsigned)W_)
                m1 = bits[(b * H_ + grow) * W_ + gcol];
        }
    }

    // --- tile geometry within the smem halo ---
    const int r0s = 2 * (ty >> 1);       // tile top row in smem
    const int c0s = tx & ~1;             // tile left col in smem
    const int ph  = ty & 1, pw = tx & 1; // position in 2x2 output tile

    unsigned long long sm = 0ull;        // own spike mask
    unsigned long long win = 0ull;       // bit j-1 = spike at t-j

#pragma unroll 2
    for (int t = 0; t < T_; ++t) {
        float* buf = &s_psp[t & 1][0][0];

        // psp for this thread's halo locations (descending lag j, +0 taps kept)
        {
            unsigned long long mt = m0 << (63 - t);   // bit 63-j == bit t-j of m0
            float acc = 0.0f;
#pragma unroll
            for (int k = 0; k < FIRN; ++k) {
                int j = FIRN - 1 - k;
                if ((mt >> (63 - j)) & 1ull) acc = __fadd_rn(acc, kk[j]);
            }
            buf[hr0 * 72 + hc0] = acc;
        }
        if (i1 < NHALO) {
            unsigned long long mt = m1 << (63 - t);
            float acc = 0.0f;
#pragma unroll
            for (int k = 0; k < FIRN; ++k) {
                int j = FIRN - 1 - k;
                if ((mt >> (63 - j)) & 1ull) acc = __fadd_rn(acc, kk[j]);
            }
            buf[hr1 * 72 + hc1] = acc;
        }
        __syncthreads();

        // Winograd input transform (identical op order to R6)
        float tt[4][4];
#pragma unroll
        for (int c = 0; c < 4; ++c) {
            float x0 = buf[(r0s + 0) * 72 + c0s + c];
            float x1 = buf[(r0s + 1) * 72 + c0s + c];
            float x2 = buf[(r0s + 2) * 72 + c0s + c];
            float x3 = buf[(r0s + 3) * 72 + c0s + c];
            tt[0][c] = __fsub_rn(x0, x2);
            tt[1][c] = __fadd_rn(x1, x2);
            tt[2][c] = __fsub_rn(x2, x1);
            tt[3][c] = __fsub_rn(x1, x3);
        }

        float s[4];
#pragma unroll
        for (int j = 0; j < 4; ++j) {
            float M[4];
#pragma unroll
            for (int i = 0; i < 4; ++i) {
                float t0 = tt[i][0], t1 = tt[i][1], t2 = tt[i][2], t3 = tt[i][3];
                float Vij = (j == 0) ? __fsub_rn(t0, t2)
                          : (j == 1) ? __fadd_rn(t1, t2)
                          : (j == 2) ? __fsub_rn(t2, t1)
                                     : __fsub_rn(t1, t3);
                M[i] = __fmul_rn(U[i][j], Vij);
            }
            s[j] = (ph == 0) ? __fadd_rn(__fadd_rn(M[0], M[1]), M[2])
                             : __fsub_rn(__fsub_rn(M[1], M[2]), M[3]);
        }
        float u = (pw == 0) ? __fadd_rn(__fadd_rn(s[0], s[1]), s[2])
                            : __fsub_rn(__fsub_rn(s[1], s[2]), s[3]);

        // refractory: sequential adds, spike-time ascending = lag descending
        float r = 0.0f;
#pragma unroll
        for (int j = JMAX; j >= 1; --j)
            if ((win >> (j - 1)) & 1ull) r = __fadd_rn(r, rk[j]);

        float m = __fadd_rn(u, r);
        unsigned long long sp = (m >= THETA) ? 1ull : 0ull;
        sm |= sp << t;
        win = (win << 1) | sp;
    }

    const int h   = h0 + ty;
    const int loc = (b * H_ + h) * W_ + tx;

    if (LAYER == 0) {
        g_s1bits[loc] = sm;
    } else {
        // expand bits -> floats with coalesced stores (warp shuffle transpose)
        const int lane = tx & 31;
        const int loc0 = loc - lane;
        const size_t gbase = (size_t)loc0 * T_;
        const unsigned lo32 = (unsigned)sm;
        const unsigned hi32 = (unsigned)(sm >> 32);
#pragma unroll
        for (int i = 0; i < 64; ++i) {
            int j = i >> 1;
            unsigned half = __shfl_sync(0xffffffffu, (i & 1) ? hi32 : lo32, j);
            out[gbase + i * 32 + lane] = ((half >> lane) & 1u) ? 1.0f : 0.0f;
        }
    }
}

// ---------------------------------------------------------------------------
extern "C" void kernel_launch(void* const* d_in, const int* in_sizes, int n_in,
                              void* d_out, int out_size) {
    const float* x  = (const float*)d_in[0];
    const float* w1 = (const float*)d_in[1];
    const float* w2 = (const float*)d_in[2];
    float* out = (float*)d_out;

    dim3 blk(64, 4);
    dim3 grd(H_ / 4, B_);

    pack_kernel<<<grd, blk>>>(x);
    fused_kernel<0><<<grd, blk>>>(w1, nullptr);
    fused_kernel<1><<<grd, blk>>>(w2, out);
}

// round 9
// speedup vs baseline: 3.2493x; 1.2802x over previous
#include <cuda_runtime.h>
#include <math.h>

#define B_   16
#define H_   128
#define W_   64
#define T_   64
#define NLOC (B_ * H_ * W_)

// Scratch: spike bitmasks (1 bit per timestep)
__device__ unsigned long long g_xbits[NLOC];
__device__ unsigned long long g_s1bits[NLOC];

// ---------------------------------------------------------------------------
// Kernel 0: pack input floats (exactly 0.0 / 1.0) into per-neuron bitmasks.
// ---------------------------------------------------------------------------
__global__ void __launch_bounds__(256) pack_kernel(const float* __restrict__ in) {
    const int lane = threadIdx.x & 31;
    const int w0   = threadIdx.x & 32;
    const int h    = blockIdx.x * 4 + threadIdx.y;
    const int b    = blockIdx.y;
    const int loc0 = (b * H_ + h) * W_ + w0;
    const size_t gbase = (size_t)loc0 * T_;

    unsigned lo = 0u, hi = 0u;
#pragma unroll
    for (int i = 0; i < 64; ++i) {
        float v = in[gbase + i * 32 + lane];
        unsigned bal = __ballot_sync(0xffffffffu, v != 0.0f);
        if (lane == (i >> 1)) {
            if (i & 1) hi = bal; else lo = bal;
        }
    }
    g_xbits[loc0 + lane] = ((unsigned long long)hi << 32) | (unsigned long long)lo;
}

// ---------------------------------------------------------------------------
// Fused layer kernel, thread-per-2x2-Winograd-tile.
// Block: 128 threads = 4 tile-rows x 32 tile-cols -> 8 rows x 64 cols outputs.
// psp staged in smem per 8-timestep chunk (bit-identical descending-lag FIR);
// Winograd F(2x2,3x3) op sequence identical to R6/R7; refractory = sequential
// descending-j predicated adds (== reference buffer-scan order).
// ---------------------------------------------------------------------------
template <int LAYER>
__global__ void __launch_bounds__(128) fused_kernel(const float* __restrict__ wconv,
                                                    float* __restrict__ out) {
    constexpr int   FIRN  = (LAYER == 0) ? 8 : 16;
    constexpr int   JMAX  = (LAYER == 0) ? 17 : 35;
    constexpr float THETA = (LAYER == 0) ? 30.0f : 50.0f;
    constexpr int   HR    = 10;             // halo rows  (8 + 2)
    constexpr int   HC    = 66;             // halo cols  (64 + 2)
    constexpr int   NH    = HR * HC;        // 660 halo locations
    constexpr int   TC    = 8;              // timestep chunk

    // s_buf FIRST and 16B-aligned: float2 accesses into it require 8B alignment
    __shared__ __align__(16) float s_buf[TC][HR][72];   // psp tile, padded cols
    __shared__ float s_kk[FIRN];
    __shared__ float s_rk[JMAX + 1];
    __shared__ float s_w[9];

    const int tid = threadIdx.x;
    const int h0  = blockIdx.x * 8;
    const int b   = blockIdx.y;

    // --- taps in double, matching numpy exactly ---
    {
        const double tau   = (LAYER == 0) ? 1.0 : 2.0;
        const double rmult = (LAYER == 0) ? -60.0 : -100.0;  // -2*theta*scale_ref
        if (tid < FIRN) {
            double td = (double)tid;
            s_kk[tid] = (float)(((1.0 * td) / tau) * exp(1.0 - td / tau));
        }
        if (tid <= JMAX) {
            double td = (double)tid;
            double v  = ((rmult * td) / tau) * exp(1.0 - td / tau);
            s_rk[tid] = (tid == 0) ? 0.0f : (float)v;
        }
        if (tid < 9) s_w[tid] = wconv[tid];
    }
    __syncthreads();

    float kk[FIRN];
#pragma unroll
    for (int k = 0; k < FIRN; ++k) kk[k] = s_kk[k];
    float rk[JMAX + 1];
#pragma unroll
    for (int j = 0; j <= JMAX; ++j) rk[j] = s_rk[j];

    // --- weight transform U = G g G^T, exact-half form (identical to R6) ---
    float U[4][4];
    {
        float q[4][3];
#pragma unroll
        for (int j = 0; j < 3; ++j) {
            float g0 = s_w[j], g1 = s_w[3 + j], g2 = s_w[6 + j];
            float s  = __fadd_rn(g0, g2);
            q[0][j] = g0;
            q[1][j] = __fmul_rn(0.5f, __fadd_rn(s, g1));
            q[2][j] = __fmul_rn(0.5f, __fsub_rn(s, g1));
            q[3][j] = g2;
        }
#pragma unroll
        for (int i = 0; i < 4; ++i) {
            float q0 = q[i][0], q1 = q[i][1], q2 = q[i][2];
            float s  = __fadd_rn(q0, q2);
            U[i][0] = q0;
            U[i][1] = __fmul_rn(0.5f, __fadd_rn(s, q1));
            U[i][2] = __fmul_rn(0.5f, __fsub_rn(s, q1));
            U[i][3] = q2;
        }
    }

    // --- halo bitmask load: rows h0-1..h0+8, cols -1..64, zeros outside ---
    const unsigned long long* bits = (LAYER == 0) ? g_xbits : g_s1bits;
    unsigned long long hm[6];
    int soff[6];
#pragma unroll
    for (int k = 0; k < 6; ++k) {
        int l  = tid + 128 * k;
        int hr = l / HC, hc = l % HC;
        bool valid = (l < NH);
        int grow = h0 - 1 + hr, gcol = hc - 1;
        unsigned long long v = 0ull;
        if (valid && (unsigned)grow < (unsigned)H_ && (unsigned)gcol < (unsigned)W_)
            v = bits[(b * H_ + grow) * W_ + gcol];
        hm[k]   = v;
        soff[k] = valid ? hr * 72 + hc : 9 * 72 + 66;   // pad slot if invalid
    }

    const int tr   = tid >> 5;           // tile row 0..3
    const int tcix = tid & 31;           // tile col 0..31
    const int row0 = 2 * tr;             // halo row of tile top
    const int col0 = 2 * tcix;           // halo col of tile left

    unsigned long long sm[4]  = {0ull, 0ull, 0ull, 0ull};
    unsigned long long win[4] = {0ull, 0ull, 0ull, 0ull};

    for (int tb = 0; tb < T_; tb += TC) {
        // ---- psp fill (descending lag j; j=0 tap is exactly 0 -> skipped) ----
#pragma unroll
        for (int k = 0; k < 6; ++k) {
            unsigned long long mk = hm[k];
            float* dst = &s_buf[0][0][0] + soff[k];
#pragma unroll 4
            for (int dt = 0; dt < TC; ++dt) {
                int t = tb + dt;
                unsigned long long mt = mk << (63 - t);  // bit 63-j == spike t-j
                float acc = 0.0f;
#pragma unroll
                for (int ki = 0; ki < FIRN - 1; ++ki) {
                    int j = FIRN - 1 - ki;
                    if ((mt >> (63 - j)) & 1ull) acc = __fadd_rn(acc, kk[j]);
                }
                dst[dt * (HR * 72)] = acc;
            }
        }
        __syncthreads();

        // ---- consume: Winograd + spike scan, 4 outputs per thread ----
#pragma unroll 4
        for (int dt = 0; dt < TC; ++dt) {
            int t = tb + dt;

            float rx[4][4];
#pragma unroll
            for (int r = 0; r < 4; ++r) {
                float2 a = *(const float2*)&s_buf[dt][row0 + r][col0];
                float2 c = *(const float2*)&s_buf[dt][row0 + r][col0 + 2];
                rx[r][0] = a.x; rx[r][1] = a.y; rx[r][2] = c.x; rx[r][3] = c.y;
            }

            float tt[4][4];
#pragma unroll
            for (int c = 0; c < 4; ++c) {
                tt[0][c] = __fsub_rn(rx[0][c], rx[2][c]);
                tt[1][c] = __fadd_rn(rx[1][c], rx[2][c]);
                tt[2][c] = __fsub_rn(rx[2][c], rx[1][c]);
                tt[3][c] = __fsub_rn(rx[1][c], rx[3][c]);
            }

            float s0[4], s1[4];
#pragma unroll
            for (int j = 0; j < 4; ++j) {
                float M[4];
#pragma unroll
                for (int i = 0; i < 4; ++i) {
                    float t0 = tt[i][0], t1 = tt[i][1], t2 = tt[i][2], t3 = tt[i][3];
                    float Vij = (j == 0) ? __fsub_rn(t0, t2)
                              : (j == 1) ? __fadd_rn(t1, t2)
                              : (j == 2) ? __fsub_rn(t2, t1)
                                         : __fsub_rn(t1, t3);
                    M[i] = __fmul_rn(U[i][j], Vij);
                }
                s0[j] = __fadd_rn(__fadd_rn(M[0], M[1]), M[2]);
                s1[j] = __fsub_rn(__fsub_rn(M[1], M[2]), M[3]);
            }
            float y[4];
            y[0] = __fadd_rn(__fadd_rn(s0[0], s0[1]), s0[2]);   // (0,0)
            y[1] = __fsub_rn(__fsub_rn(s0[1], s0[2]), s0[3]);   // (0,1)
            y[2] = __fadd_rn(__fadd_rn(s1[0], s1[1]), s1[2]);   // (1,0)
            y[3] = __fsub_rn(__fsub_rn(s1[1], s1[2]), s1[3]);   // (1,1)

#pragma unroll
            for (int p = 0; p < 4; ++p) {
                float r = 0.0f;
#pragma unroll
                for (int j = JMAX; j >= 1; --j)
                    if ((win[p] >> (j - 1)) & 1ull) r = __fadd_rn(r, rk[j]);
                float m = __fadd_rn(y[p], r);
                unsigned long long sp = (m >= THETA) ? 1ull : 0ull;
                sm[p]  |= sp << t;
                win[p]  = (win[p] << 1) | sp;
            }
        }
        __syncthreads();
    }

    // ---- epilogue ----
#pragma unroll
    for (int p = 0; p < 4; ++p) {
        const int h   = h0 + 2 * tr + (p >> 1);
        const int wc  = 2 * tcix + (p & 1);
        const int loc = (b * H_ + h) * W_ + wc;
        if (LAYER == 0) {
            g_s1bits[loc] = sm[p];
        } else {
            float4* o = (float4*)(out + (size_t)loc * T_);
            const unsigned long long s = sm[p];
#pragma unroll
            for (int i = 0; i < 16; ++i) {
                float4 v;
                v.x = ((s >> (4 * i + 0)) & 1ull) ? 1.0f : 0.0f;
                v.y = ((s >> (4 * i + 1)) & 1ull) ? 1.0f : 0.0f;
                v.z = ((s >> (4 * i + 2)) & 1ull) ? 1.0f : 0.0f;
                v.w = ((s >> (4 * i + 3)) & 1ull) ? 1.0f : 0.0f;
                o[i] = v;
            }
        }
    }
}

// ---------------------------------------------------------------------------
extern "C" void kernel_launch(void* const* d_in, const int* in_sizes, int n_in,
                              void* d_out, int out_size) {
    const float* x  = (const float*)d_in[0];
    const float* w1 = (const float*)d_in[1];
    const float* w2 = (const float*)d_in[2];
    float* out = (float*)d_out;

    dim3 pblk(64, 4), pgrd(H_ / 4, B_);
    pack_kernel<<<pgrd, pblk>>>(x);

    dim3 fblk(128), fgrd(H_ / 8, B_);
    fused_kernel<0><<<fgrd, fblk>>>(w1, nullptr);
    fused_kernel<1><<<fgrd, fblk>>>(w2, out);
}